// round 16
// baseline (speedup 1.0000x reference)
#include <cuda_runtime.h>
#include <cuda_fp16.h>
#include <mma.h>
#include <cstdint>
#include <math.h>

using namespace nvcuda;

#define NN 100000
#define NN2 100352   // padded row count (multiple of 256) for unguarded tile stores
#define EE 1600000
#define NB_SCAN 98   // ceil(NN/1024)

// ---------------- scratch (device globals; no runtime allocation) ----------------
__device__ int   g_deg[NN];
__device__ int   g_rowp[NN + 1];
__device__ int   g_cur[NN];
__device__ int   g_bsum[NB_SCAN];
__device__ __align__(16) int2 g_epack[EE];   // {src, bitcast(dinv[src])}
__device__ float g_dinv[NN];
__device__ float g_mu[NN];
__device__ float g_rs[NN];
__device__ float g_sA[NN];
__device__ float g_sA2[NN];
__device__ __align__(16) __half g_t [NN2 * 128];   // fp16 pre-agg intermediate
__device__ float g_h1[NN2 * 128];
__device__ float g_h2[NN2 * 128];
__device__ __align__(16) __half g_t2[NN2 * 64];
// packed fp16 weights: per chunk [32 x NPADP]
__device__ __align__(16) __half g_wh0[20 * 32 * 136];
__device__ __align__(16) __half g_wh1[20 * 32 * 136];
__device__ __align__(16) __half g_wh2[60 * 32 * 56];

// ---------------- async-copy helpers ----------------
__device__ __forceinline__ uint32_t smem_u32(const void* p) {
    uint32_t a;
    asm("{ .reg .u64 t; cvta.to.shared.u64 t, %1; cvt.u32.u64 %0, t; }"
        : "=r"(a) : "l"(p));
    return a;
}
__device__ __forceinline__ void cpasync16(uint32_t dst, const void* src) {
    asm volatile("cp.async.cg.shared.global [%0], [%1], 16;" :: "r"(dst), "l"(src));
}
#define CPCOMMIT() asm volatile("cp.async.commit_group;" ::: "memory")
#define CPWAIT0()  asm volatile("cp.async.wait_group 0;" ::: "memory")

// ---------------- stats of x + zero deg (fused) ----------------
__global__ void k_statx(const float* __restrict__ x) {
    int gt = blockIdx.x * blockDim.x + threadIdx.x;
    if (gt < NN) g_deg[gt] = 0;
    int gw = gt >> 5;
    int lane = threadIdx.x & 31;
    if (gw >= NN) return;
    float4 v = ((const float4*)(x + (size_t)gw * 128))[lane];
    float s  = v.x + v.y + v.z + v.w;
    float s2 = v.x * v.x + v.y * v.y + v.z * v.z + v.w * v.w;
    #pragma unroll
    for (int d = 16; d; d >>= 1) {
        s  += __shfl_xor_sync(0xffffffffu, s,  d);
        s2 += __shfl_xor_sync(0xffffffffu, s2, d);
    }
    if (lane == 0) {
        float m = s * (1.f / 128.f);
        g_mu[gw] = m;
        g_rs[gw] = rsqrtf(s2 * (1.f / 128.f) - m * m + 1e-5f);
        g_sA[gw]  = s;
        g_sA2[gw] = s2;
    }
}

// ---------------- graph preprocessing ----------------
__global__ void k_count(const int* __restrict__ ei) {
    int e4 = blockIdx.x * blockDim.x + threadIdx.x;
    if (e4 * 4 >= EE) return;
    int4 d = ((const int4*)(ei + EE))[e4];
    atomicAdd(&g_deg[d.x], 1);
    atomicAdd(&g_deg[d.y], 1);
    atomicAdd(&g_deg[d.z], 1);
    atomicAdd(&g_deg[d.w], 1);
}
__global__ void k_scan1() {
    __shared__ int wsum[32];
    int t = threadIdx.x, lane = t & 31, wid = t >> 5;
    int i = blockIdx.x * 1024 + t;
    int v = (i < NN) ? g_deg[i] : 0;
    int x = v;
    #pragma unroll
    for (int d = 1; d < 32; d <<= 1) {
        int y = __shfl_up_sync(0xffffffffu, x, d);
        if (lane >= d) x += y;
    }
    if (lane == 31) wsum[wid] = x;
    __syncthreads();
    if (wid == 0) {
        int ws = wsum[lane];
        #pragma unroll
        for (int d = 1; d < 32; d <<= 1) {
            int y = __shfl_up_sync(0xffffffffu, ws, d);
            if (lane >= d) ws += y;
        }
        wsum[lane] = ws;
    }
    __syncthreads();
    int excl = (wid ? wsum[wid - 1] : 0) + (x - v);
    if (i < NN) g_rowp[i] = excl;
    if (t == 0) g_bsum[blockIdx.x] = wsum[31];
}
__global__ void k_scan2() {
    __shared__ int sh[128];
    int t = threadIdx.x;
    int v = (t < NB_SCAN) ? g_bsum[t] : 0;
    int x = v;
    sh[t] = x;
    __syncthreads();
    #pragma unroll
    for (int d = 1; d < 128; d <<= 1) {
        int y = (t >= d) ? sh[t - d] : 0;
        __syncthreads();
        x += y;
        sh[t] = x;
        __syncthreads();
    }
    if (t < NB_SCAN) g_bsum[t] = x - v;
    if (t == NB_SCAN - 1) g_rowp[NN] = x;
}
__global__ void k_scan3() {
    int i = blockIdx.x * 1024 + threadIdx.x;
    if (i < NN) {
        int r = g_rowp[i] + g_bsum[blockIdx.x];
        g_rowp[i] = r;
        g_cur[i]  = r;
        g_dinv[i] = rsqrtf((float)(g_deg[i] + 1));
    }
}
// 4 edges per thread; pack {src, dinv[src]} per slot
__global__ void k_place(const int* __restrict__ ei) {
    int e4 = blockIdx.x * blockDim.x + threadIdx.x;
    if (e4 * 4 >= EE) return;
    int4 s = ((const int4*)ei)[e4];
    int4 d = ((const int4*)(ei + EE))[e4];
    g_epack[atomicAdd(&g_cur[d.x], 1)] = make_int2(s.x, __float_as_int(g_dinv[s.x]));
    g_epack[atomicAdd(&g_cur[d.y], 1)] = make_int2(s.y, __float_as_int(g_dinv[s.y]));
    g_epack[atomicAdd(&g_cur[d.z], 1)] = make_int2(s.z, __float_as_int(g_dinv[s.z]));
    g_epack[atomicAdd(&g_cur[d.w], 1)] = make_int2(s.w, __float_as_int(g_dinv[s.w]));
}

// ---------------- weight precompute: all 3 layers in one kernel ----------------
#define PW0 87040    // 20*32*136
#define PW1 87040
#define PW2 107520   // 60*32*56
template<int DIN, int DOUT, int NPADP>
__device__ __forceinline__ void prepw_one(const float* Wb, const float* Ws,
                                          __half* dst, int idx) {
    int n = idx % NPADP;
    int k = (idx / NPADP) & 31;
    int c = idx / (NPADP * 32);
    int kg = c * 32 + k;
    float w = 0.f;
    if (n < DOUT) {
        if (kg < DIN) w = Wb[(size_t)n * DIN + kg];
        else          w = Ws[(size_t)n * (DIN * 4) + (kg - DIN)];
    }
    dst[idx] = __float2half_rn(w);
}
__global__ void k_prepw_all(const float* __restrict__ Wb0, const float* __restrict__ Ws0,
                            const float* __restrict__ Wb1, const float* __restrict__ Ws1,
                            const float* __restrict__ Wb2, const float* __restrict__ Ws2,
                            __half* __restrict__ d0, __half* __restrict__ d1,
                            __half* __restrict__ d2) {
    int idx = blockIdx.x * blockDim.x + threadIdx.x;
    if (idx < PW0) {
        prepw_one<128, 128, 136>(Wb0, Ws0, d0, idx);
    } else if (idx < PW0 + PW1) {
        prepw_one<128, 128, 136>(Wb1, Ws1, d1, idx - PW0);
    } else if (idx < PW0 + PW1 + PW2) {
        prepw_one<384, 47, 56>(Wb2, Ws2, d2, idx - PW0 - PW1);
    }
}

// ---------------- fused FastKAN layer via wmma fp16 (single term) ----------------
__device__ __forceinline__ void halfstore(__half* p, float4 v) {
    __half2 h0 = __floats2half2_rn(v.x, v.y);
    __half2 h1 = __floats2half2_rn(v.z, v.w);
    ((__half2*)p)[0] = h0;
    ((__half2*)p)[1] = h1;
}

// Double-buffered stages: [A TM*ALD fp16][B 32*NPADP fp16][xbuf TM*32 f32].
// Epilogue: acc frags -> smem (reuse stage mem) -> fp16 gmem (padded NN2 rows).
template<int DIN, int DOUT, int NPAD, int NPADP, int OUT_STRIDE, int WM,
         int TM, int THREADS>
__global__ void __launch_bounds__(THREADS, 512 / THREADS)
k_fkan_wmma(const float* __restrict__ in0, const float* __restrict__ in1,
            const float* __restrict__ in2,
            const float* __restrict__ lng, const float* __restrict__ lnb,
            const __half* __restrict__ wp,
            __half* __restrict__ out)
{
    constexpr int NCH   = DIN * 5 / 32;
    constexpr int NT    = NPAD / 16;
    constexpr int WARPS = THREADS / 32;
    constexpr int WN    = WARPS / WM;
    constexpr int MT    = (TM / 16) / WM;
    constexpr int NTW   = NT / WN;
    static_assert(WM * WN == WARPS && MT * WM * 16 == TM && NTW * WN == NT, "tiling");
    constexpr int ALD  = 40;
    constexpr int AELE = TM * ALD;
    constexpr int BELE = 32 * NPADP;
    constexpr int XOFF = (AELE + BELE) * 2;
    constexpr int STB  = XOFF + TM * 32 * 4;
    constexpr int OUTS = NPAD + 8;                  // epilogue smem stride (floats)

    extern __shared__ char smc[];
    const uint32_t sbase = smem_u32(smc);

    const int t = threadIdx.x;
    const int w = t >> 5;
    const int wm = w % WM, wn = w / WM;
    const int base = blockIdx.x * TM;

    const int rsp = t >> 1, gsp = t & 1;
    int nsp = base + rsp; if (nsp >= NN) nsp = NN - 1;
    const float mu = g_mu[nsp];
    const float rs = g_rs[nsp];

    wmma::fragment<wmma::accumulator, 16, 16, 16, float> acc[MT][NTW];
    #pragma unroll
    for (int im = 0; im < MT; im++)
        #pragma unroll
        for (int in = 0; in < NTW; in++) wmma::fill_fragment(acc[im][in], 0.f);

    auto stageB = [&](int c, int s) {
        constexpr int NV4 = BELE * 2 / 16;
        const char* src = (const char*)(wp + (size_t)c * BELE);
        const uint32_t dst = sbase + s * STB + AELE * 2;
        #pragma unroll
        for (int i = t; i < NV4; i += THREADS)
            cpasync16(dst + i * 16, src + i * 16);
    };
    auto stageX = [&](int c, int s) {
        const uint32_t xdst = sbase + s * STB + XOFF;
        const int kc = c * 32;
        if (kc < DIN) {
            const float* srcp; int colbase;
            if (DIN == 128) { srcp = in0; colbase = kc; }
            else {
                int blk = kc >> 7;
                srcp = (blk == 0) ? in0 : (blk == 1) ? in1 : in2;
                colbase = kc & 127;
            }
            #pragma unroll
            for (int i = 0; i < (TM * 8) / THREADS; i++) {
                int idx = t + i * THREADS;
                int row = idx >> 3, g = idx & 7;
                int nr = base + row; if (nr >= NN) nr = NN - 1;
                cpasync16(xdst + idx * 16, srcp + (size_t)nr * 128 + colbase + g * 4);
            }
        } else {
            int xc0 = (kc - DIN) >> 2;
            const float* srcp; int colbase;
            if (DIN == 128) { srcp = in0; colbase = xc0; }
            else {
                int blk = xc0 >> 7;
                srcp = (blk == 0) ? in0 : (blk == 1) ? in1 : in2;
                colbase = xc0 & 127;
            }
            cpasync16(xdst + t * 16, srcp + (size_t)nsp * 128 + colbase + gsp * 4);
        }
    };
    auto computeA = [&](int c, int s) {
        __half* aH = (__half*)(smc + s * STB);
        const float* xb = (const float*)(smc + s * STB + XOFF);
        const int kc = c * 32;
        if (kc < DIN) {
            #pragma unroll
            for (int i = 0; i < (TM * 8) / THREADS; i++) {
                int idx = t + i * THREADS;
                int row = idx >> 3, g = idx & 7;
                float4 xv = *(const float4*)(xb + idx * 4);
                float4 v;
                v.x = __fdividef(xv.x, 1.f + __expf(-xv.x));
                v.y = __fdividef(xv.y, 1.f + __expf(-xv.y));
                v.z = __fdividef(xv.z, 1.f + __expf(-xv.z));
                v.w = __fdividef(xv.w, 1.f + __expf(-xv.w));
                halfstore(aH + row * ALD + g * 4, v);
            }
        } else {
            float4 xv = *(const float4*)(xb + t * 4);
            const int xc = ((kc - DIN) >> 2) + gsp * 4;
            const float4 gv = *(const float4*)(lng + xc);
            const float4 bv = *(const float4*)(lnb + xc);
            float zz[4];
            zz[0] = (xv.x - mu) * rs * gv.x + bv.x;
            zz[1] = (xv.y - mu) * rs * gv.y + bv.y;
            zz[2] = (xv.z - mu) * rs * gv.z + bv.z;
            zz[3] = (xv.w - mu) * rs * gv.w + bv.w;
            #pragma unroll
            for (int i = 0; i < 4; i++) {
                const float z = zz[i];
                const float zp2 = z + 2.f;
                const float r0 = __expf(-0.5625f * zp2 * zp2);
                const float B  = __expf(1.5f * z);
                float4 v;
                v.x = r0;
                v.y = r0 * B * 7.3890560989f;
                v.z = v.y * B;
                v.w = v.z * B * 0.1353352832f;
                halfstore(aH + rsp * ALD + gsp * 16 + i * 4, v);
            }
        }
    };

    stageB(0, 0);
    stageX(0, 0);
    CPCOMMIT();
    CPWAIT0();
    computeA(0, 0);
    __syncthreads();

    for (int c = 0; c < NCH; c++) {
        const int s = c & 1;
        if (c + 1 < NCH) {
            stageB(c + 1, 1 - s);
            stageX(c + 1, 1 - s);
            CPCOMMIT();
        }

        {
            __half* aH = (__half*)(smc + s * STB);
            __half* bB = aH + AELE;
            #pragma unroll
            for (int kk = 0; kk < 2; kk++) {
                wmma::fragment<wmma::matrix_a, 16, 16, 16, __half, wmma::row_major> af[MT];
                #pragma unroll
                for (int im = 0; im < MT; im++)
                    wmma::load_matrix_sync(af[im],
                        aH + (wm * MT + im) * 16 * ALD + kk * 16, ALD);
                #pragma unroll
                for (int in = 0; in < NTW; in++) {
                    wmma::fragment<wmma::matrix_b, 16, 16, 16, __half, wmma::row_major> bf;
                    wmma::load_matrix_sync(bf,
                        bB + kk * 16 * NPADP + (wn * NTW + in) * 16, NPADP);
                    #pragma unroll
                    for (int im = 0; im < MT; im++)
                        wmma::mma_sync(acc[im][in], af[im], bf, acc[im][in]);
                }
            }
        }

        CPWAIT0();
        if (c + 1 < NCH) computeA(c + 1, 1 - s);
        __syncthreads();
    }

    // ---- epilogue: acc -> smem (float) -> fp16 gmem ----
    float* sOut = (float*)smc;
    #pragma unroll
    for (int im = 0; im < MT; im++)
        #pragma unroll
        for (int in = 0; in < NTW; in++)
            wmma::store_matrix_sync(
                sOut + ((wm * MT + im) * 16) * OUTS + (wn * NTW + in) * 16,
                acc[im][in], OUTS, wmma::mem_row_major);
    __syncthreads();

    constexpr int HP = NPAD / 2;   // half2 per row
    for (int e = t; e < TM * HP; e += THREADS) {
        int row = e / HP, j = e % HP;
        const float* sp = sOut + row * OUTS + j * 2;
        __half2 h = __floats2half2_rn(sp[0], sp[1]);
        *(__half2*)(out + (size_t)(base + row) * OUT_STRIDE + j * 2) = h;
    }
}

// ---------------- aggregation (packed edges, fp16 gather) + fused stats ----------------
__global__ void k_agg128(const __half* __restrict__ tin, float* __restrict__ outp,
                         const float* __restrict__ bs, const float* __restrict__ bb,
                         const float* __restrict__ bg, int statmode) {
    int gw = (blockIdx.x * blockDim.x + threadIdx.x) >> 5;
    int lane = threadIdx.x & 31;
    if (gw >= NN) return;
    int beg = g_rowp[gw], end = g_rowp[gw + 1];
    float4 a = make_float4(0.f, 0.f, 0.f, 0.f);
    float sw = 0.f;
    int j = beg;
    for (; j + 7 < end; j += 8) {
        int2  ep[8];
        uint2 ui[8];
        #pragma unroll
        for (int q = 0; q < 8; q++) ep[q] = g_epack[j + q];
        #pragma unroll
        for (int q = 0; q < 8; q++)
            ui[q] = ((const uint2*)(tin + (size_t)ep[q].x * 128))[lane];
        #pragma unroll
        for (int q = 0; q < 8; q++) {
            float wq = __int_as_float(ep[q].y);
            sw += wq;
            float2 fa = __half22float2(*(__half2*)&ui[q].x);
            float2 fb = __half22float2(*(__half2*)&ui[q].y);
            a.x += wq * fa.x;
            a.y += wq * fa.y;
            a.z += wq * fb.x;
            a.w += wq * fb.y;
        }
    }
    for (; j < end; j++) {
        int2 ep = g_epack[j];
        float w0 = __int_as_float(ep.y);
        sw += w0;
        uint2 u0 = ((const uint2*)(tin + (size_t)ep.x * 128))[lane];
        float2 f0a = __half22float2(*(__half2*)&u0.x), f0b = __half22float2(*(__half2*)&u0.y);
        a.x += w0 * f0a.x; a.y += w0 * f0a.y; a.z += w0 * f0b.x; a.w += w0 * f0b.y;
    }
    float dn = g_dinv[gw];
    float wb = dn * (sw + dn);
    uint2 us = ((const uint2*)(tin + (size_t)gw * 128))[lane];
    float2 fsa = __half22float2(*(__half2*)&us.x), fsb = __half22float2(*(__half2*)&us.y);
    float4 bgv = ((const float4*)bg)[lane];
    float4 bsv = ((const float4*)bs)[lane];
    float4 bbv = ((const float4*)bb)[lane];
    float4 o;
    o.x = dn * (a.x + dn * fsa.x) + (bsv.x + bbv.x) * wb + bgv.x;
    o.y = dn * (a.y + dn * fsa.y) + (bsv.y + bbv.y) * wb + bgv.y;
    o.z = dn * (a.z + dn * fsb.x) + (bsv.z + bbv.z) * wb + bgv.z;
    o.w = dn * (a.w + dn * fsb.y) + (bsv.w + bbv.w) * wb + bgv.w;
    ((float4*)outp)[(size_t)gw * 32 + lane] = o;

    float s  = o.x + o.y + o.z + o.w;
    float s2 = o.x * o.x + o.y * o.y + o.z * o.z + o.w * o.w;
    #pragma unroll
    for (int d = 16; d; d >>= 1) {
        s  += __shfl_xor_sync(0xffffffffu, s,  d);
        s2 += __shfl_xor_sync(0xffffffffu, s2, d);
    }
    if (lane == 0) {
        if (statmode == 1) {
            float m = s * (1.f / 128.f);
            g_mu[gw] = m;
            g_rs[gw] = rsqrtf(s2 * (1.f / 128.f) - m * m + 1e-5f);
            g_sA[gw]  += s;
            g_sA2[gw] += s2;
        } else {
            float ts  = g_sA[gw]  + s;
            float ts2 = g_sA2[gw] + s2;
            float m = ts * (1.f / 384.f);
            g_mu[gw] = m;
            g_rs[gw] = rsqrtf(ts2 * (1.f / 384.f) - m * m + 1e-5f);
        }
    }
}

// lane handles column pair (2*lane, 2*lane+1); lanes >= 24 guarded out.
__global__ void k_agg47(const __half* __restrict__ tin, float* __restrict__ outp,
                        const float* __restrict__ bs, const float* __restrict__ bb,
                        const float* __restrict__ bg) {
    int gw = (blockIdx.x * blockDim.x + threadIdx.x) >> 5;
    int lane = threadIdx.x & 31;
    if (gw >= NN) return;
    int beg = g_rowp[gw], end = g_rowp[gw + 1];
    float a0 = 0.f, a1 = 0.f, sw = 0.f;
    int j = beg;
    for (; j + 3 < end; j += 4) {
        int2 e0 = g_epack[j], e1 = g_epack[j + 1], e2 = g_epack[j + 2], e3 = g_epack[j + 3];
        float w0 = __int_as_float(e0.y), w1 = __int_as_float(e1.y);
        float w2 = __int_as_float(e2.y), w3 = __int_as_float(e3.y);
        sw += w0 + w1 + w2 + w3;
        float2 f0 = __half22float2(((const __half2*)(tin + (size_t)e0.x * 64))[lane]);
        float2 f1 = __half22float2(((const __half2*)(tin + (size_t)e1.x * 64))[lane]);
        float2 f2 = __half22float2(((const __half2*)(tin + (size_t)e2.x * 64))[lane]);
        float2 f3 = __half22float2(((const __half2*)(tin + (size_t)e3.x * 64))[lane]);
        a0 += w0 * f0.x + w1 * f1.x + w2 * f2.x + w3 * f3.x;
        a1 += w0 * f0.y + w1 * f1.y + w2 * f2.y + w3 * f3.y;
    }
    for (; j < end; j++) {
        int2 e0 = g_epack[j];
        float w0 = __int_as_float(e0.y);
        sw += w0;
        float2 f0 = __half22float2(((const __half2*)(tin + (size_t)e0.x * 64))[lane]);
        a0 += w0 * f0.x;
        a1 += w0 * f0.y;
    }
    float dn = g_dinv[gw];
    float wb = dn * (sw + dn);
    float2 fs = __half22float2(((const __half2*)(tin + (size_t)gw * 64))[lane]);
    int c0 = lane * 2, c1 = c0 + 1;
    if (c0 < 47)
        outp[(size_t)gw * 47 + c0] =
            dn * (a0 + dn * fs.x) + (bs[c0] + bb[c0]) * wb + bg[c0];
    if (c1 < 47)
        outp[(size_t)gw * 47 + c1] =
            dn * (a1 + dn * fs.y) + (bs[c1] + bb[c1]) * wb + bg[c1];
}

// ---------------- driver ----------------
extern "C" void kernel_launch(void* const* d_in, const int* in_sizes, int n_in,
                              void* d_out, int out_size) {
    const float* x    = (const float*)d_in[0];
    const int*   ei   = (const int*)d_in[1];
    const float* lng0 = (const float*)d_in[2];
    const float* lnb0 = (const float*)d_in[3];
    const float* Ws0  = (const float*)d_in[4];
    const float* bs0  = (const float*)d_in[5];
    const float* Wb0  = (const float*)d_in[6];
    const float* bb0  = (const float*)d_in[7];
    const float* bg0  = (const float*)d_in[8];
    const float* lng1 = (const float*)d_in[9];
    const float* lnb1 = (const float*)d_in[10];
    const float* Ws1  = (const float*)d_in[11];
    const float* bs1  = (const float*)d_in[12];
    const float* Wb1  = (const float*)d_in[13];
    const float* bb1  = (const float*)d_in[14];
    const float* bg1  = (const float*)d_in[15];
    const float* lng2 = (const float*)d_in[16];
    const float* lnb2 = (const float*)d_in[17];
    const float* Ws2  = (const float*)d_in[18];
    const float* bs2  = (const float*)d_in[19];
    const float* Wb2  = (const float*)d_in[20];
    const float* bb2  = (const float*)d_in[21];
    const float* bg2  = (const float*)d_in[22];
    float* outp = (float*)d_out;

    void *pt, *ph1, *ph2, *pt2, *pw0, *pw1, *pw2;
    cudaGetSymbolAddress(&pt,  g_t);
    cudaGetSymbolAddress(&ph1, g_h1);
    cudaGetSymbolAddress(&ph2, g_h2);
    cudaGetSymbolAddress(&pt2, g_t2);
    cudaGetSymbolAddress(&pw0, g_wh0);
    cudaGetSymbolAddress(&pw1, g_wh1);
    cudaGetSymbolAddress(&pw2, g_wh2);

    const int STG_L01 = 2 * ((128 * 40 + 32 * 136) * 2 + 128 * 32 * 4);  // 70656
    const int EPI_L01 = 128 * 136 * 4;                                    // 69632
    const int SM_L01  = STG_L01 > EPI_L01 ? STG_L01 : EPI_L01;
    const int STG_L2  = 2 * ((128 * 40 + 32 * 56) * 2 + 128 * 32 * 4);   // 60416
    const int EPI_L2  = 128 * 56 * 4;                                     // 28672
    const int SM_L2   = STG_L2 > EPI_L2 ? STG_L2 : EPI_L2;
    cudaFuncSetAttribute(
        (const void*)k_fkan_wmma<128, 128, 128, 136, 128, 4, 128, 256>,
        cudaFuncAttributeMaxDynamicSharedMemorySize, SM_L01);
    cudaFuncSetAttribute(
        (const void*)k_fkan_wmma<384, 47, 48, 56, 64, 8, 128, 256>,
        cudaFuncAttributeMaxDynamicSharedMemorySize, SM_L2);

    const int FG01 = (NN + 127) / 128;        // 782
    const int SG   = (NN * 32 + 255) / 256;   // warp per node
    const int EG4  = (EE / 4 + 255) / 256;    // 4 edges per thread
    const int PWG  = (PW0 + PW1 + PW2 + 255) / 256;

    // launches 1-3 (ncu profiles launch #4 -> keep it fkan layer-0)
    k_statx<<<SG, 256>>>(x);               // also zeroes g_deg
    k_prepw_all<<<PWG, 256>>>(Wb0, Ws0, Wb1, Ws1, Wb2, Ws2,
                              (__half*)pw0, (__half*)pw1, (__half*)pw2);
    k_count<<<EG4, 256>>>(ei);

    // launch #4: layer-0 fkan (PROFILED)
    k_fkan_wmma<128, 128, 128, 136, 128, 4, 128, 256><<<FG01, 256, SM_L01>>>(
        x, nullptr, nullptr, lng0, lnb0, (const __half*)pw0, (__half*)pt);

    // remaining prep
    k_scan1<<<NB_SCAN, 1024>>>();
    k_scan2<<<1, 128>>>();
    k_scan3<<<NB_SCAN, 1024>>>();
    k_place<<<EG4, 256>>>(ei);

    k_agg128<<<SG, 256>>>((const __half*)pt, (float*)ph1, bs0, bb0, bg0, 1);

    // layer 1
    k_fkan_wmma<128, 128, 128, 136, 128, 4, 128, 256><<<FG01, 256, SM_L01>>>(
        (const float*)ph1, nullptr, nullptr, lng1, lnb1, (const __half*)pw1,
        (__half*)pt);
    k_agg128<<<SG, 256>>>((const __half*)pt, (float*)ph2, bs1, bb1, bg1, 2);

    // layer 2
    k_fkan_wmma<384, 47, 48, 56, 64, 8, 128, 256><<<FG01, 256, SM_L2>>>(
        x, (const float*)ph1, (const float*)ph2, lng2, lnb2,
        (const __half*)pw2, (__half*)pt2);
    k_agg47<<<SG, 256>>>((const __half*)pt2, outp, bs2, bb2, bg2);
}

// round 17
// speedup vs baseline: 1.0360x; 1.0360x over previous
#include <cuda_runtime.h>
#include <cuda_fp16.h>
#include <mma.h>
#include <cstdint>
#include <math.h>

using namespace nvcuda;

#define NN 100000
#define NN2 100352   // padded row count (multiple of 256) for unguarded tile stores
#define EE 1600000
#define NB_SCAN 98   // ceil(NN/1024)

// ---------------- scratch (device globals; no runtime allocation) ----------------
__device__ int   g_deg[NN];
__device__ int   g_rowp[NN + 1];
__device__ int   g_cur[NN];
__device__ int   g_bsum[NB_SCAN];
__device__ int   g_esrc[EE];
__device__ float g_dinv[NN];
__device__ float g_mu[NN];
__device__ float g_rs[NN];
__device__ float g_sA[NN];
__device__ float g_sA2[NN];
__device__ __align__(16) __half g_t [NN2 * 128];   // fp16 pre-agg intermediate
__device__ float g_h1[NN2 * 128];
__device__ float g_h2[NN2 * 128];
__device__ __align__(16) __half g_t2[NN2 * 64];
// packed fp16 weights: per chunk [32 x NPADP]
__device__ __align__(16) __half g_wh0[20 * 32 * 136];
__device__ __align__(16) __half g_wh1[20 * 32 * 136];
__device__ __align__(16) __half g_wh2[60 * 32 * 56];

// ---------------- helpers ----------------
__device__ __forceinline__ uint32_t smem_u32(const void* p) {
    uint32_t a;
    asm("{ .reg .u64 t; cvta.to.shared.u64 t, %1; cvt.u32.u64 %0, t; }"
        : "=r"(a) : "l"(p));
    return a;
}
__device__ __forceinline__ void cpasync16(uint32_t dst, const void* src) {
    asm volatile("cp.async.cg.shared.global [%0], [%1], 16;" :: "r"(dst), "l"(src));
}
#define CPCOMMIT() asm volatile("cp.async.commit_group;" ::: "memory")
#define CPWAIT0()  asm volatile("cp.async.wait_group 0;" ::: "memory")

__device__ __forceinline__ float fast_tanh(float x) {
    float r;
    asm("tanh.approx.f32 %0, %1;" : "=f"(r) : "f"(x));
    return r;
}
__device__ __forceinline__ float fast_silu(float x) {
    return x * (0.5f * fast_tanh(0.5f * x) + 0.5f);
}

// ---------------- stats of x + zero deg (fused) ----------------
__global__ void k_statx(const float* __restrict__ x) {
    int gt = blockIdx.x * blockDim.x + threadIdx.x;
    if (gt < NN) g_deg[gt] = 0;
    int gw = gt >> 5;
    int lane = threadIdx.x & 31;
    if (gw >= NN) return;
    float4 v = ((const float4*)(x + (size_t)gw * 128))[lane];
    float s  = v.x + v.y + v.z + v.w;
    float s2 = v.x * v.x + v.y * v.y + v.z * v.z + v.w * v.w;
    #pragma unroll
    for (int d = 16; d; d >>= 1) {
        s  += __shfl_xor_sync(0xffffffffu, s,  d);
        s2 += __shfl_xor_sync(0xffffffffu, s2, d);
    }
    if (lane == 0) {
        float m = s * (1.f / 128.f);
        g_mu[gw] = m;
        g_rs[gw] = rsqrtf(s2 * (1.f / 128.f) - m * m + 1e-5f);
        g_sA[gw]  = s;
        g_sA2[gw] = s2;
    }
}

// ---------------- graph preprocessing ----------------
__global__ void k_count(const int* __restrict__ ei) {
    int e4 = blockIdx.x * blockDim.x + threadIdx.x;
    if (e4 * 4 >= EE) return;
    int4 d = ((const int4*)(ei + EE))[e4];
    atomicAdd(&g_deg[d.x], 1);
    atomicAdd(&g_deg[d.y], 1);
    atomicAdd(&g_deg[d.z], 1);
    atomicAdd(&g_deg[d.w], 1);
}
__global__ void k_scan1() {
    __shared__ int wsum[32];
    int t = threadIdx.x, lane = t & 31, wid = t >> 5;
    int i = blockIdx.x * 1024 + t;
    int v = (i < NN) ? g_deg[i] : 0;
    int x = v;
    #pragma unroll
    for (int d = 1; d < 32; d <<= 1) {
        int y = __shfl_up_sync(0xffffffffu, x, d);
        if (lane >= d) x += y;
    }
    if (lane == 31) wsum[wid] = x;
    __syncthreads();
    if (wid == 0) {
        int ws = wsum[lane];
        #pragma unroll
        for (int d = 1; d < 32; d <<= 1) {
            int y = __shfl_up_sync(0xffffffffu, ws, d);
            if (lane >= d) ws += y;
        }
        wsum[lane] = ws;
    }
    __syncthreads();
    int excl = (wid ? wsum[wid - 1] : 0) + (x - v);
    if (i < NN) g_rowp[i] = excl;
    if (t == 0) g_bsum[blockIdx.x] = wsum[31];
}
__global__ void k_scan2() {
    __shared__ int sh[128];
    int t = threadIdx.x;
    int v = (t < NB_SCAN) ? g_bsum[t] : 0;
    int x = v;
    sh[t] = x;
    __syncthreads();
    #pragma unroll
    for (int d = 1; d < 128; d <<= 1) {
        int y = (t >= d) ? sh[t - d] : 0;
        __syncthreads();
        x += y;
        sh[t] = x;
        __syncthreads();
    }
    if (t < NB_SCAN) g_bsum[t] = x - v;
    if (t == NB_SCAN - 1) g_rowp[NN] = x;
}
__global__ void k_scan3() {
    int i = blockIdx.x * 1024 + threadIdx.x;
    if (i < NN) {
        int r = g_rowp[i] + g_bsum[blockIdx.x];
        g_rowp[i] = r;
        g_cur[i]  = r;
        g_dinv[i] = rsqrtf((float)(g_deg[i] + 1));
    }
}
__global__ void k_place(const int* __restrict__ ei) {
    int e4 = blockIdx.x * blockDim.x + threadIdx.x;
    if (e4 * 4 >= EE) return;
    int4 s = ((const int4*)ei)[e4];
    int4 d = ((const int4*)(ei + EE))[e4];
    g_esrc[atomicAdd(&g_cur[d.x], 1)] = s.x;
    g_esrc[atomicAdd(&g_cur[d.y], 1)] = s.y;
    g_esrc[atomicAdd(&g_cur[d.z], 1)] = s.z;
    g_esrc[atomicAdd(&g_cur[d.w], 1)] = s.w;
}

// ---------------- weight precompute: all 3 layers in one kernel ----------------
#define PW0 87040    // 20*32*136
#define PW1 87040
#define PW2 107520   // 60*32*56
template<int DIN, int DOUT, int NPADP>
__device__ __forceinline__ void prepw_one(const float* Wb, const float* Ws,
                                          __half* dst, int idx) {
    int n = idx % NPADP;
    int k = (idx / NPADP) & 31;
    int c = idx / (NPADP * 32);
    int kg = c * 32 + k;
    float w = 0.f;
    if (n < DOUT) {
        if (kg < DIN) w = Wb[(size_t)n * DIN + kg];
        else          w = Ws[(size_t)n * (DIN * 4) + (kg - DIN)];
    }
    dst[idx] = __float2half_rn(w);
}
__global__ void k_prepw_all(const float* __restrict__ Wb0, const float* __restrict__ Ws0,
                            const float* __restrict__ Wb1, const float* __restrict__ Ws1,
                            const float* __restrict__ Wb2, const float* __restrict__ Ws2,
                            __half* __restrict__ d0, __half* __restrict__ d1,
                            __half* __restrict__ d2) {
    int idx = blockIdx.x * blockDim.x + threadIdx.x;
    if (idx < PW0) {
        prepw_one<128, 128, 136>(Wb0, Ws0, d0, idx);
    } else if (idx < PW0 + PW1) {
        prepw_one<128, 128, 136>(Wb1, Ws1, d1, idx - PW0);
    } else if (idx < PW0 + PW1 + PW2) {
        prepw_one<384, 47, 56>(Wb2, Ws2, d2, idx - PW0 - PW1);
    }
}

// ---------------- fused FastKAN layer via wmma fp16 (single term) ----------------
__device__ __forceinline__ void halfstore(__half* p, float4 v) {
    __half2 h0 = __floats2half2_rn(v.x, v.y);
    __half2 h1 = __floats2half2_rn(v.z, v.w);
    ((__half2*)p)[0] = h0;
    ((__half2*)p)[1] = h1;
}

// Double-buffered stages: [A TM*ALD fp16][B 32*NPADP fp16][xbuf TM*32 f32].
// Epilogue: acc frags -> smem (reuse stage mem) -> fp16 gmem (padded NN2 rows).
template<int DIN, int DOUT, int NPAD, int NPADP, int OUT_STRIDE, int WM,
         int TM, int THREADS>
__global__ void __launch_bounds__(THREADS, 512 / THREADS)
k_fkan_wmma(const float* __restrict__ in0, const float* __restrict__ in1,
            const float* __restrict__ in2,
            const float* __restrict__ lng, const float* __restrict__ lnb,
            const __half* __restrict__ wp,
            __half* __restrict__ out)
{
    constexpr int NCH   = DIN * 5 / 32;
    constexpr int NT    = NPAD / 16;
    constexpr int WARPS = THREADS / 32;
    constexpr int WN    = WARPS / WM;
    constexpr int MT    = (TM / 16) / WM;
    constexpr int NTW   = NT / WN;
    static_assert(WM * WN == WARPS && MT * WM * 16 == TM && NTW * WN == NT, "tiling");
    constexpr int ALD  = 40;
    constexpr int AELE = TM * ALD;
    constexpr int BELE = 32 * NPADP;
    constexpr int XOFF = (AELE + BELE) * 2;
    constexpr int STB  = XOFF + TM * 32 * 4;
    constexpr int OUTS = NPAD + 8;                  // epilogue smem stride (floats)

    extern __shared__ char smc[];
    const uint32_t sbase = smem_u32(smc);

    const int t = threadIdx.x;
    const int w = t >> 5;
    const int wm = w % WM, wn = w / WM;
    const int base = blockIdx.x * TM;

    const int rsp = t >> 1, gsp = t & 1;
    int nsp = base + rsp; if (nsp >= NN) nsp = NN - 1;
    const float mu = g_mu[nsp];
    const float rs = g_rs[nsp];

    wmma::fragment<wmma::accumulator, 16, 16, 16, float> acc[MT][NTW];
    #pragma unroll
    for (int im = 0; im < MT; im++)
        #pragma unroll
        for (int in = 0; in < NTW; in++) wmma::fill_fragment(acc[im][in], 0.f);

    auto stageB = [&](int c, int s) {
        constexpr int NV4 = BELE * 2 / 16;
        const char* src = (const char*)(wp + (size_t)c * BELE);
        const uint32_t dst = sbase + s * STB + AELE * 2;
        #pragma unroll
        for (int i = t; i < NV4; i += THREADS)
            cpasync16(dst + i * 16, src + i * 16);
    };
    auto stageX = [&](int c, int s) {
        const uint32_t xdst = sbase + s * STB + XOFF;
        const int kc = c * 32;
        if (kc < DIN) {
            const float* srcp; int colbase;
            if (DIN == 128) { srcp = in0; colbase = kc; }
            else {
                int blk = kc >> 7;
                srcp = (blk == 0) ? in0 : (blk == 1) ? in1 : in2;
                colbase = kc & 127;
            }
            #pragma unroll
            for (int i = 0; i < (TM * 8) / THREADS; i++) {
                int idx = t + i * THREADS;
                int row = idx >> 3, g = idx & 7;
                int nr = base + row; if (nr >= NN) nr = NN - 1;
                cpasync16(xdst + idx * 16, srcp + (size_t)nr * 128 + colbase + g * 4);
            }
        } else {
            int xc0 = (kc - DIN) >> 2;
            const float* srcp; int colbase;
            if (DIN == 128) { srcp = in0; colbase = xc0; }
            else {
                int blk = xc0 >> 7;
                srcp = (blk == 0) ? in0 : (blk == 1) ? in1 : in2;
                colbase = xc0 & 127;
            }
            cpasync16(xdst + t * 16, srcp + (size_t)nsp * 128 + colbase + gsp * 4);
        }
    };
    auto computeA = [&](int c, int s) {
        __half* aH = (__half*)(smc + s * STB);
        const float* xb = (const float*)(smc + s * STB + XOFF);
        const int kc = c * 32;
        if (kc < DIN) {
            #pragma unroll
            for (int i = 0; i < (TM * 8) / THREADS; i++) {
                int idx = t + i * THREADS;
                int row = idx >> 3, g = idx & 7;
                float4 xv = *(const float4*)(xb + idx * 4);
                float4 v;
                v.x = fast_silu(xv.x);
                v.y = fast_silu(xv.y);
                v.z = fast_silu(xv.z);
                v.w = fast_silu(xv.w);
                halfstore(aH + row * ALD + g * 4, v);
            }
        } else {
            float4 xv = *(const float4*)(xb + t * 4);
            const int xc = ((kc - DIN) >> 2) + gsp * 4;
            const float4 gv = *(const float4*)(lng + xc);
            const float4 bv = *(const float4*)(lnb + xc);
            float zz[4];
            zz[0] = (xv.x - mu) * rs * gv.x + bv.x;
            zz[1] = (xv.y - mu) * rs * gv.y + bv.y;
            zz[2] = (xv.z - mu) * rs * gv.z + bv.z;
            zz[3] = (xv.w - mu) * rs * gv.w + bv.w;
            #pragma unroll
            for (int i = 0; i < 4; i++) {
                const float z = zz[i];
                const float zp2 = z + 2.f;
                const float r0 = __expf(-0.5625f * zp2 * zp2);
                const float B  = __expf(1.5f * z);
                float4 v;
                v.x = r0;
                v.y = r0 * B * 7.3890560989f;
                v.z = v.y * B;
                v.w = v.z * B * 0.1353352832f;
                halfstore(aH + rsp * ALD + gsp * 16 + i * 4, v);
            }
        }
    };

    stageB(0, 0);
    stageX(0, 0);
    CPCOMMIT();
    CPWAIT0();
    computeA(0, 0);
    __syncthreads();

    for (int c = 0; c < NCH; c++) {
        const int s = c & 1;
        if (c + 1 < NCH) {
            stageB(c + 1, 1 - s);
            stageX(c + 1, 1 - s);
            CPCOMMIT();
        }

        {
            __half* aH = (__half*)(smc + s * STB);
            __half* bB = aH + AELE;
            #pragma unroll
            for (int kk = 0; kk < 2; kk++) {
                wmma::fragment<wmma::matrix_a, 16, 16, 16, __half, wmma::row_major> af[MT];
                #pragma unroll
                for (int im = 0; im < MT; im++)
                    wmma::load_matrix_sync(af[im],
                        aH + (wm * MT + im) * 16 * ALD + kk * 16, ALD);
                #pragma unroll
                for (int in = 0; in < NTW; in++) {
                    wmma::fragment<wmma::matrix_b, 16, 16, 16, __half, wmma::row_major> bf;
                    wmma::load_matrix_sync(bf,
                        bB + kk * 16 * NPADP + (wn * NTW + in) * 16, NPADP);
                    #pragma unroll
                    for (int im = 0; im < MT; im++)
                        wmma::mma_sync(acc[im][in], af[im], bf, acc[im][in]);
                }
            }
        }

        CPWAIT0();
        if (c + 1 < NCH) computeA(c + 1, 1 - s);
        __syncthreads();
    }

    // ---- epilogue: acc -> smem (float) -> fp16 gmem ----
    float* sOut = (float*)smc;
    #pragma unroll
    for (int im = 0; im < MT; im++)
        #pragma unroll
        for (int in = 0; in < NTW; in++)
            wmma::store_matrix_sync(
                sOut + ((wm * MT + im) * 16) * OUTS + (wn * NTW + in) * 16,
                acc[im][in], OUTS, wmma::mem_row_major);
    __syncthreads();

    constexpr int HP = NPAD / 2;   // half2 per row
    for (int e = t; e < TM * HP; e += THREADS) {
        int row = e / HP, j = e % HP;
        const float* sp = sOut + row * OUTS + j * 2;
        __half2 h = __floats2half2_rn(sp[0], sp[1]);
        *(__half2*)(out + (size_t)(base + row) * OUT_STRIDE + j * 2) = h;
    }
}

// ---------------- aggregation (fp16 gather, 8-deep unroll) + fused stats ----------------
__global__ void k_agg128(const __half* __restrict__ tin, float* __restrict__ outp,
                         const float* __restrict__ bs, const float* __restrict__ bb,
                         const float* __restrict__ bg, int statmode) {
    int gw = (blockIdx.x * blockDim.x + threadIdx.x) >> 5;
    int lane = threadIdx.x & 31;
    if (gw >= NN) return;
    int beg = g_rowp[gw], end = g_rowp[gw + 1];
    float4 a = make_float4(0.f, 0.f, 0.f, 0.f);
    float sw = 0.f;
    int j = beg;
    for (; j + 7 < end; j += 8) {
        int   si[8];
        float wi[8];
        uint2 ui[8];
        #pragma unroll
        for (int q = 0; q < 8; q++) si[q] = g_esrc[j + q];
        #pragma unroll
        for (int q = 0; q < 8; q++) {
            wi[q] = g_dinv[si[q]];
            ui[q] = ((const uint2*)(tin + (size_t)si[q] * 128))[lane];
        }
        #pragma unroll
        for (int q = 0; q < 8; q++) {
            sw += wi[q];
            float2 fa = __half22float2(*(__half2*)&ui[q].x);
            float2 fb = __half22float2(*(__half2*)&ui[q].y);
            a.x += wi[q] * fa.x;
            a.y += wi[q] * fa.y;
            a.z += wi[q] * fb.x;
            a.w += wi[q] * fb.y;
        }
    }
    for (; j < end; j++) {
        int s0 = g_esrc[j];
        float w0 = g_dinv[s0];
        sw += w0;
        uint2 u0 = ((const uint2*)(tin + (size_t)s0 * 128))[lane];
        float2 f0a = __half22float2(*(__half2*)&u0.x), f0b = __half22float2(*(__half2*)&u0.y);
        a.x += w0 * f0a.x; a.y += w0 * f0a.y; a.z += w0 * f0b.x; a.w += w0 * f0b.y;
    }
    float dn = g_dinv[gw];
    float wb = dn * (sw + dn);
    uint2 us = ((const uint2*)(tin + (size_t)gw * 128))[lane];
    float2 fsa = __half22float2(*(__half2*)&us.x), fsb = __half22float2(*(__half2*)&us.y);
    float4 bgv = ((const float4*)bg)[lane];
    float4 bsv = ((const float4*)bs)[lane];
    float4 bbv = ((const float4*)bb)[lane];
    float4 o;
    o.x = dn * (a.x + dn * fsa.x) + (bsv.x + bbv.x) * wb + bgv.x;
    o.y = dn * (a.y + dn * fsa.y) + (bsv.y + bbv.y) * wb + bgv.y;
    o.z = dn * (a.z + dn * fsb.x) + (bsv.z + bbv.z) * wb + bgv.z;
    o.w = dn * (a.w + dn * fsb.y) + (bsv.w + bbv.w) * wb + bgv.w;
    ((float4*)outp)[(size_t)gw * 32 + lane] = o;

    float s  = o.x + o.y + o.z + o.w;
    float s2 = o.x * o.x + o.y * o.y + o.z * o.z + o.w * o.w;
    #pragma unroll
    for (int d = 16; d; d >>= 1) {
        s  += __shfl_xor_sync(0xffffffffu, s,  d);
        s2 += __shfl_xor_sync(0xffffffffu, s2, d);
    }
    if (lane == 0) {
        if (statmode == 1) {
            float m = s * (1.f / 128.f);
            g_mu[gw] = m;
            g_rs[gw] = rsqrtf(s2 * (1.f / 128.f) - m * m + 1e-5f);
            g_sA[gw]  += s;
            g_sA2[gw] += s2;
        } else {
            float ts  = g_sA[gw]  + s;
            float ts2 = g_sA2[gw] + s2;
            float m = ts * (1.f / 384.f);
            g_mu[gw] = m;
            g_rs[gw] = rsqrtf(ts2 * (1.f / 384.f) - m * m + 1e-5f);
        }
    }
}

// lane handles column pair (2*lane, 2*lane+1); lanes >= 24 guarded out.
__global__ void k_agg47(const __half* __restrict__ tin, float* __restrict__ outp,
                        const float* __restrict__ bs, const float* __restrict__ bb,
                        const float* __restrict__ bg) {
    int gw = (blockIdx.x * blockDim.x + threadIdx.x) >> 5;
    int lane = threadIdx.x & 31;
    if (gw >= NN) return;
    int beg = g_rowp[gw], end = g_rowp[gw + 1];
    float a0 = 0.f, a1 = 0.f, sw = 0.f;
    int j = beg;
    for (; j + 3 < end; j += 4) {
        int s0 = g_esrc[j], s1 = g_esrc[j + 1], s2 = g_esrc[j + 2], s3 = g_esrc[j + 3];
        float w0 = g_dinv[s0], w1 = g_dinv[s1], w2 = g_dinv[s2], w3 = g_dinv[s3];
        sw += w0 + w1 + w2 + w3;
        float2 f0 = __half22float2(((const __half2*)(tin + (size_t)s0 * 64))[lane]);
        float2 f1 = __half22float2(((const __half2*)(tin + (size_t)s1 * 64))[lane]);
        float2 f2 = __half22float2(((const __half2*)(tin + (size_t)s2 * 64))[lane]);
        float2 f3 = __half22float2(((const __half2*)(tin + (size_t)s3 * 64))[lane]);
        a0 += w0 * f0.x + w1 * f1.x + w2 * f2.x + w3 * f3.x;
        a1 += w0 * f0.y + w1 * f1.y + w2 * f2.y + w3 * f3.y;
    }
    for (; j < end; j++) {
        int s0 = g_esrc[j];
        float w0 = g_dinv[s0];
        sw += w0;
        float2 f0 = __half22float2(((const __half2*)(tin + (size_t)s0 * 64))[lane]);
        a0 += w0 * f0.x;
        a1 += w0 * f0.y;
    }
    float dn = g_dinv[gw];
    float wb = dn * (sw + dn);
    float2 fs = __half22float2(((const __half2*)(tin + (size_t)gw * 64))[lane]);
    int c0 = lane * 2, c1 = c0 + 1;
    if (c0 < 47)
        outp[(size_t)gw * 47 + c0] =
            dn * (a0 + dn * fs.x) + (bs[c0] + bb[c0]) * wb + bg[c0];
    if (c1 < 47)
        outp[(size_t)gw * 47 + c1] =
            dn * (a1 + dn * fs.y) + (bs[c1] + bb[c1]) * wb + bg[c1];
}

// ---------------- driver ----------------
extern "C" void kernel_launch(void* const* d_in, const int* in_sizes, int n_in,
                              void* d_out, int out_size) {
    const float* x    = (const float*)d_in[0];
    const int*   ei   = (const int*)d_in[1];
    const float* lng0 = (const float*)d_in[2];
    const float* lnb0 = (const float*)d_in[3];
    const float* Ws0  = (const float*)d_in[4];
    const float* bs0  = (const float*)d_in[5];
    const float* Wb0  = (const float*)d_in[6];
    const float* bb0  = (const float*)d_in[7];
    const float* bg0  = (const float*)d_in[8];
    const float* lng1 = (const float*)d_in[9];
    const float* lnb1 = (const float*)d_in[10];
    const float* Ws1  = (const float*)d_in[11];
    const float* bs1  = (const float*)d_in[12];
    const float* Wb1  = (const float*)d_in[13];
    const float* bb1  = (const float*)d_in[14];
    const float* bg1  = (const float*)d_in[15];
    const float* lng2 = (const float*)d_in[16];
    const float* lnb2 = (const float*)d_in[17];
    const float* Ws2  = (const float*)d_in[18];
    const float* bs2  = (const float*)d_in[19];
    const float* Wb2  = (const float*)d_in[20];
    const float* bb2  = (const float*)d_in[21];
    const float* bg2  = (const float*)d_in[22];
    float* outp = (float*)d_out;

    void *pt, *ph1, *ph2, *pt2, *pw0, *pw1, *pw2;
    cudaGetSymbolAddress(&pt,  g_t);
    cudaGetSymbolAddress(&ph1, g_h1);
    cudaGetSymbolAddress(&ph2, g_h2);
    cudaGetSymbolAddress(&pt2, g_t2);
    cudaGetSymbolAddress(&pw0, g_wh0);
    cudaGetSymbolAddress(&pw1, g_wh1);
    cudaGetSymbolAddress(&pw2, g_wh2);

    const int STG_L01 = 2 * ((128 * 40 + 32 * 136) * 2 + 128 * 32 * 4);  // 70656
    const int EPI_L01 = 128 * 136 * 4;                                    // 69632
    const int SM_L01  = STG_L01 > EPI_L01 ? STG_L01 : EPI_L01;
    const int STG_L2  = 2 * ((128 * 40 + 32 * 56) * 2 + 128 * 32 * 4);   // 60416
    const int EPI_L2  = 128 * 56 * 4;                                     // 28672
    const int SM_L2   = STG_L2 > EPI_L2 ? STG_L2 : EPI_L2;
    cudaFuncSetAttribute(
        (const void*)k_fkan_wmma<128, 128, 128, 136, 128, 4, 128, 256>,
        cudaFuncAttributeMaxDynamicSharedMemorySize, SM_L01);
    cudaFuncSetAttribute(
        (const void*)k_fkan_wmma<384, 47, 48, 56, 64, 8, 128, 256>,
        cudaFuncAttributeMaxDynamicSharedMemorySize, SM_L2);

    const int FG01 = (NN + 127) / 128;        // 782
    const int SG   = (NN * 32 + 255) / 256;   // warp per node
    const int EG4  = (EE / 4 + 255) / 256;    // 4 edges per thread
    const int PWG  = (PW0 + PW1 + PW2 + 255) / 256;

    // launches 1-3 (ncu profiles launch #4 -> keep it fkan layer-0)
    k_statx<<<SG, 256>>>(x);               // also zeroes g_deg
    k_prepw_all<<<PWG, 256>>>(Wb0, Ws0, Wb1, Ws1, Wb2, Ws2,
                              (__half*)pw0, (__half*)pw1, (__half*)pw2);
    k_count<<<EG4, 256>>>(ei);

    // launch #4: layer-0 fkan (PROFILED)
    k_fkan_wmma<128, 128, 128, 136, 128, 4, 128, 256><<<FG01, 256, SM_L01>>>(
        x, nullptr, nullptr, lng0, lnb0, (const __half*)pw0, (__half*)pt);

    // remaining prep
    k_scan1<<<NB_SCAN, 1024>>>();
    k_scan2<<<1, 128>>>();
    k_scan3<<<NB_SCAN, 1024>>>();
    k_place<<<EG4, 256>>>(ei);

    k_agg128<<<SG, 256>>>((const __half*)pt, (float*)ph1, bs0, bb0, bg0, 1);

    // layer 1
    k_fkan_wmma<128, 128, 128, 136, 128, 4, 128, 256><<<FG01, 256, SM_L01>>>(
        (const float*)ph1, nullptr, nullptr, lng1, lnb1, (const __half*)pw1,
        (__half*)pt);
    k_agg128<<<SG, 256>>>((const __half*)pt, (float*)ph2, bs1, bb1, bg1, 2);

    // layer 2
    k_fkan_wmma<384, 47, 48, 56, 64, 8, 128, 256><<<FG01, 256, SM_L2>>>(
        x, (const float*)ph1, (const float*)ph2, lng2, lnb2,
        (const __half*)pw2, (__half*)pt2);
    k_agg47<<<SG, 256>>>((const __half*)pt2, outp, bs2, bb2, bg2);
}